// round 7
// baseline (speedup 1.0000x reference)
#include <cuda_runtime.h>
#include <cuda_bf16.h>
#include <cstdint>

// -------- constants from the reference --------
#define POOL_SIZE   32
#define PROMPT_LEN  32
#define NCTX        32
#define EMBED       768
#define TOP_K       5
#define N_CLS       1000
#define SUFFIX_LEN  12
#define EMBED_F4    (EMBED / 4)          // 192
#define CLS_F4      14784u               // 77*192
#define PROMPTS_F4  14784000u            // 1000*14784
#define SUF_F4      2304u                // 12*192

// Phase A rows (LDG/STG path): prefix 1000 + suffix 12000 + pool/key 1056
#define NROWS_A     14056u
#define GRID_X      148                  // one wave, 1 block/SM
#define BLOCK_X     1024

#define CMB_F4      (PROMPT_LEN * EMBED_F4)  // 6144 f4 = 96 KB
#define CTX_F4      (NCTX * EMBED_F4)        // 6144 f4 = 96 KB
#define TILE_BYTES  98304u                   // 96 KB
#define DYN_SMEM_BYTES ((CMB_F4 + CTX_F4) * 16)   // 192 KB

// -------- device scratch / sync state (zero-init at load) --------
__device__ float4 g_combined4[CMB_F4];
__device__ int      g_flag;
__device__ unsigned g_done;

// ---- async bulk store helpers (SMEM -> GMEM, engine-driven) ----
__device__ __forceinline__ void bulk_store(void* gdst, uint32_t ssrc, uint32_t bytes)
{
    asm volatile("cp.async.bulk.global.shared::cta.bulk_group [%0], [%1], %2;"
                 :: "l"(gdst), "r"(ssrc), "r"(bytes) : "memory");
}
__device__ __forceinline__ void bulk_commit()
{
    asm volatile("cp.async.bulk.commit_group;" ::: "memory");
}
__device__ __forceinline__ void bulk_wait_all()
{
    asm volatile("cp.async.bulk.wait_group 0;" ::: "memory");
}
__device__ __forceinline__ void fence_async_proxy()
{
    asm volatile("fence.proxy.async.shared::cta;" ::: "memory");
}

// Row copy: 192 float4 per warp => 6 per lane (512B per instruction)
__device__ __forceinline__
void copy_row_stream(const float4* __restrict__ src, float4* __restrict__ dst, int lane)
{
    float4 v[6];
    #pragma unroll
    for (int i = 0; i < 6; ++i) v[i] = __ldcs(&src[lane + i * 32]);
    #pragma unroll
    for (int i = 0; i < 6; ++i) __stcs(&dst[lane + i * 32], v[i]);
}

// ============================================================
// Block 0's work: selection + gating + combined (1024 thr)
// Writes to g_combined4 (for other blocks) and cmb_s (own smem).
// ============================================================
__device__ __forceinline__
void compute_combined(const float4* __restrict__ x4,
                      const float4* __restrict__ key4,
                      const float4* __restrict__ pool4,
                      const float4* __restrict__ aw4,
                      const float*  __restrict__ ab,
                      float4* __restrict__ cmb_s,
                      float4 (&qs4)[EMBED_F4],
                      float4 (&aw_s)[EMBED_F4],
                      float  (&sim)[POOL_SIZE],
                      int    (&idxs)[TOP_K])
{
    const int t = threadIdx.x;
    const int w = t >> 5, lane = t & 31;

    // ---- q = sum over 16 frames (mean scale & q-norm don't affect top-k)
    if (t < EMBED_F4) {
        float4 s = make_float4(0.f, 0.f, 0.f, 0.f);
        #pragma unroll
        for (int f = 0; f < 16; ++f) {
            float4 v = __ldg(&x4[f * EMBED_F4 + t]);
            s.x += v.x; s.y += v.y; s.z += v.z; s.w += v.w;
        }
        qs4[t] = s;
        aw_s[t] = __ldg(&aw4[t]);
    }
    __syncthreads();

    // ---- one warp per pool key: sim = (k.q)/||k|| (cosine-order equivalent)
    {
        const float4* kp = key4 + w * EMBED_F4;
        float dot = 0.f, nrm = 0.f;
        #pragma unroll
        for (int i = 0; i < 6; ++i) {
            const int c = lane + i * 32;
            float4 kv = __ldg(&kp[c]), qv = qs4[c];
            dot += kv.x*qv.x + kv.y*qv.y + kv.z*qv.z + kv.w*qv.w;
            nrm += kv.x*kv.x + kv.y*kv.y + kv.z*kv.z + kv.w*kv.w;
        }
        #pragma unroll
        for (int o = 16; o; o >>= 1) {
            dot += __shfl_down_sync(0xffffffffu, dot, o);
            nrm += __shfl_down_sync(0xffffffffu, nrm, o);
        }
        if (lane == 0) sim[w] = dot * rsqrtf(nrm);
    }
    __syncthreads();

    // ---- top-5, strict '>' = lowest index wins ties (matches jax.lax.top_k)
    if (t == 0) {
        unsigned usedmask = 0u;
        for (int k = 0; k < TOP_K; ++k) {
            int best = 0; float bv = -3.0e38f;
            #pragma unroll
            for (int p = 0; p < POOL_SIZE; ++p)
                if (!((usedmask >> p) & 1u) && sim[p] > bv) { bv = sim[p]; best = p; }
            usedmask |= 1u << best;
            idxs[k] = best;
        }
    }
    __syncthreads();

    // ---- one warp per token position l = w: gates + weighted sum
    const float ab0 = ab[0];
    const float4* rows[TOP_K];
    #pragma unroll
    for (int k = 0; k < TOP_K; ++k)
        rows[k] = pool4 + (idxs[k] * PROMPT_LEN + w) * EMBED_F4;

    float dots[TOP_K] = {0.f, 0.f, 0.f, 0.f, 0.f};
    #pragma unroll
    for (int i = 0; i < 6; ++i) {
        const int c = lane + i * 32;
        float4 av = aw_s[c];
        #pragma unroll
        for (int k = 0; k < TOP_K; ++k) {
            float4 rv = __ldg(&rows[k][c]);
            dots[k] += rv.x*av.x + rv.y*av.y + rv.z*av.z + rv.w*av.w;
        }
    }
    #pragma unroll
    for (int k = 0; k < TOP_K; ++k) {
        #pragma unroll
        for (int o = 16; o; o >>= 1)
            dots[k] += __shfl_xor_sync(0xffffffffu, dots[k], o);
    }
    float wt[TOP_K];
    #pragma unroll
    for (int k = 0; k < TOP_K; ++k)
        wt[k] = 1.f / (1.f + __expf(-(dots[k] + ab0)));

    #pragma unroll
    for (int i = 0; i < 6; ++i) {
        const int c = lane + i * 32;
        float4 acc = make_float4(0.f, 0.f, 0.f, 0.f);
        #pragma unroll
        for (int k = 0; k < TOP_K; ++k) {
            float4 rv = __ldg(&rows[k][c]);      // L1 hit
            acc.x += wt[k]*rv.x; acc.y += wt[k]*rv.y;
            acc.z += wt[k]*rv.z; acc.w += wt[k]*rv.w;
        }
        g_combined4[w * EMBED_F4 + c] = acc;
        cmb_s[w * EMBED_F4 + c] = acc;
    }
}

// ============================================================
// The single persistent kernel
// ============================================================
__global__ __launch_bounds__(BLOCK_X, 1)
void k_all(const float4* __restrict__ x4,
           const float4* __restrict__ key4,
           const float4* __restrict__ pool4,
           const float4* __restrict__ aw4,
           const float*  __restrict__ ab,
           const float4* __restrict__ pre4,
           const float4* __restrict__ suf4,
           const float4* __restrict__ ctx4,
           float4* __restrict__ out)
{
    extern __shared__ float4 dyn_s[];
    float4* __restrict__ cmb_s = dyn_s;            // [CMB_F4]  rows 1..32
    float4* __restrict__ ctx_s = dyn_s + CMB_F4;   // [CTX_F4]  rows 33..64

    __shared__ float4 qs4[EMBED_F4];
    __shared__ float4 aw_s[EMBED_F4];
    __shared__ float  sim[POOL_SIZE];
    __shared__ int    idxs[TOP_K];

    const int t = threadIdx.x;
    const int w = t >> 5, lane = t & 31;
    const unsigned b = blockIdx.x;
    const unsigned nb = gridDim.x;

    const uint32_t cmb_sa = (uint32_t)__cvta_generic_to_shared(cmb_s);
    const uint32_t ctx_sa = (uint32_t)__cvta_generic_to_shared(ctx_s);
    float* outf = (float*)out;

    if (b == 0) {
        // ---- selection + gating + combined on a private SM, release flag
        compute_combined(x4, key4, pool4, aw4, ab, cmb_s, qs4, aw_s, sim, idxs);
        __syncthreads();
        __threadfence();
        if (t == 0) atomicExch(&g_flag, 1);
    }

    // ---- stage ctx into SMEM: warp w loads row w (tiny; L2-hot after first)
    {
        const float4* src = ctx4 + w * EMBED_F4;
        float4* dst = ctx_s + w * EMBED_F4;
        #pragma unroll
        for (int i = 0; i < 6; ++i) dst[lane + i * 32] = __ldg(&src[lane + i * 32]);
    }
    __syncthreads();
    fence_async_proxy();

    // ---- issue ctx bulk-stores for this block's classes (engine-driven)
    if (t == 0) {
        for (unsigned c = b; c < N_CLS; c += nb) {
            bulk_store(outf + ((size_t)c * CLS_F4 + 33u * EMBED_F4) * 4u,
                       ctx_sa, TILE_BYTES);
            bulk_commit();
        }
    }

    if (b != 0) {
        // ---- Phase A: prefix + suffix + pool/key via LDG/STG warps
        const unsigned WA = (nb - 1u) * 32u;
        for (unsigned R = (b - 1u) * 32u + (unsigned)w; R < NROWS_A; R += WA) {
            if (R < 1000u) {
                copy_row_stream(pre4 + R * EMBED_F4, out + R * CLS_F4, lane);
            } else if (R < 13000u) {
                const unsigned j = R - 1000u;
                const unsigned c = j / 12u;            // magic-multiply
                const unsigned r = j - c * 12u;
                copy_row_stream(suf4 + c * SUF_F4 + r * EMBED_F4,
                                out + c * CLS_F4 + (65u + r) * EMBED_F4, lane);
            } else {
                const unsigned q = R - 13000u;         // 0..1055: pool then key
                const float4* src = (q < 1024u) ? (pool4 + q * EMBED_F4)
                                                : (key4 + (q - 1024u) * EMBED_F4);
                copy_row_stream(src, out + PROMPTS_F4 + q * EMBED_F4, lane);
            }
        }

        // ---- wait for combined, stage it into SMEM (src L2-hot)
        if (t == 0) {
            while (atomicAdd(&g_flag, 0) == 0) __nanosleep(64);
        }
        __syncthreads();
        __threadfence();
        {
            const float4* src = g_combined4 + w * EMBED_F4;
            float4* dst = cmb_s + w * EMBED_F4;
            #pragma unroll
            for (int i = 0; i < 6; ++i) dst[lane + i * 32] = __ldg(&src[lane + i * 32]);
        }
        __syncthreads();
        fence_async_proxy();
    }
    // (block 0's cmb_s was written in compute_combined, fenced above)

    // ---- issue combined bulk-stores, then wait for all engine stores
    if (t == 0) {
        for (unsigned c = b; c < N_CLS; c += nb) {
            bulk_store(outf + ((size_t)c * CLS_F4 + EMBED_F4) * 4u,
                       cmb_sa, TILE_BYTES);
            bulk_commit();
        }
        bulk_wait_all();   // all this block's bulk stores complete
    }

    // ---- self-reset sync state so every graph replay starts clean
    __syncthreads();
    if (t == 0) {
        __threadfence();
        unsigned prev = atomicAdd(&g_done, 1u);
        if (prev == nb - 1u) { g_done = 0u; g_flag = 0; }
    }
}

// ============================================================
extern "C" void kernel_launch(void* const* d_in, const int* in_sizes, int n_in,
                              void* d_out, int out_size)
{
    const float* x_embed      = (const float*)d_in[0];
    const float* prompt_pool  = (const float*)d_in[1];
    const float* prompt_key   = (const float*)d_in[2];
    const float* alpha_w      = (const float*)d_in[3];
    const float* alpha_b      = (const float*)d_in[4];
    const float* ctx          = (const float*)d_in[5];
    const float* token_prefix = (const float*)d_in[6];
    const float* token_suffix = (const float*)d_in[7];
    // d_in[8] = train_flag: the penalty is a positive scalar on sims ->
    // top-k ordering (and therefore the output) is unchanged; safely ignored.

    static int attr_done = 0;
    if (!attr_done) {
        cudaFuncSetAttribute(k_all, cudaFuncAttributeMaxDynamicSharedMemorySize,
                             DYN_SMEM_BYTES);
        attr_done = 1;
    }

    k_all<<<GRID_X, BLOCK_X, DYN_SMEM_BYTES>>>(
        (const float4*)x_embed,
        (const float4*)prompt_key,
        (const float4*)prompt_pool,
        (const float4*)alpha_w,
        alpha_b,
        (const float4*)token_prefix,
        (const float4*)token_suffix,
        (const float4*)ctx,
        (float4*)d_out);
}

// round 8
// speedup vs baseline: 1.0224x; 1.0224x over previous
#include <cuda_runtime.h>
#include <cuda_bf16.h>

// -------- constants from the reference --------
#define POOL_SIZE   32
#define PROMPT_LEN  32
#define NCTX        32
#define EMBED       768
#define TOP_K       5
#define N_CLS       1000
#define SUFFIX_LEN  12
#define EMBED_F4    (EMBED / 4)          // 192
#define CLS_F4      14784u               // 77*192
#define PROMPTS_F4  14784000u            // 1000*14784
#define SUF_F4      2304u                // 12*192

// Row-granular work (one row = 192 float4 = 3 KB, one warp-iter, MLP=6/lane)
//   Phase A (independent of selection): 1000*45 + 1056 pool/key = 46,056 rows
//   Phase B (needs combined):           1000*32               = 32,000 rows
#define NROWS_A     46056u
#define NROWS_B     32000u
#define GRID_X      148                  // one wave, 1 block/SM
#define BLOCK_X     1024
#define CHUNK       8u                   // rows per atomic fetch

#define CTX_F4      (NCTX * EMBED_F4)        // 6144 float4 = 96 KB
#define CMB_F4      (PROMPT_LEN * EMBED_F4)  // 6144 float4 = 96 KB
#define DYN_SMEM_BYTES ((CTX_F4 + CMB_F4) * 16)

// -------- device scratch / sync state (zero-init at load) --------
__device__ float4 g_combined4[CMB_F4];
__device__ int      g_flag;
__device__ unsigned g_done;
__device__ unsigned g_qa;     // phase A work queue
__device__ unsigned g_qb;     // phase B work queue

// Row copy helpers: 192 float4 per warp => 6 per lane (512B per instruction)
__device__ __forceinline__
void copy_row_stream(const float4* __restrict__ src, float4* __restrict__ dst, int lane)
{
    float4 v[6];
    #pragma unroll
    for (int i = 0; i < 6; ++i) v[i] = __ldcs(&src[lane + i * 32]);
    #pragma unroll
    for (int i = 0; i < 6; ++i) __stcs(&dst[lane + i * 32], v[i]);
}
__device__ __forceinline__
void copy_row_smem(const float4* __restrict__ src_s, float4* __restrict__ dst, int lane)
{
    float4 v[6];
    #pragma unroll
    for (int i = 0; i < 6; ++i) v[i] = src_s[lane + i * 32];   // LDS.128
    #pragma unroll
    for (int i = 0; i < 6; ++i) __stcs(&dst[lane + i * 32], v[i]);
}

// ============================================================
// Block 0's work: selection + gating + combined (1024 threads)
// Writes result to g_combined4 (for other blocks) AND cmb_s (own smem).
// ============================================================
__device__ __forceinline__
void compute_combined(const float4* __restrict__ x4,
                      const float4* __restrict__ key4,
                      const float4* __restrict__ pool4,
                      const float4* __restrict__ aw4,
                      const float*  __restrict__ ab,
                      float4* __restrict__ cmb_s,
                      float4 (&qs4)[EMBED_F4],
                      float4 (&aw_s)[EMBED_F4],
                      float  (&sim)[POOL_SIZE],
                      int    (&idxs)[TOP_K])
{
    const int t = threadIdx.x;
    const int w = t >> 5, lane = t & 31;

    // ---- q = sum over 16 frames (mean scale & q-norm don't affect top-k)
    if (t < EMBED_F4) {
        float4 s = make_float4(0.f, 0.f, 0.f, 0.f);
        #pragma unroll
        for (int f = 0; f < 16; ++f) {
            float4 v = __ldg(&x4[f * EMBED_F4 + t]);
            s.x += v.x; s.y += v.y; s.z += v.z; s.w += v.w;
        }
        qs4[t] = s;
        aw_s[t] = __ldg(&aw4[t]);
    }
    __syncthreads();

    // ---- one warp per pool key: sim = (k.q)/||k|| (cosine-order equivalent)
    {
        const float4* kp = key4 + w * EMBED_F4;
        float dot = 0.f, nrm = 0.f;
        #pragma unroll
        for (int i = 0; i < 6; ++i) {
            const int c = lane + i * 32;
            float4 kv = __ldg(&kp[c]), qv = qs4[c];
            dot += kv.x*qv.x + kv.y*qv.y + kv.z*qv.z + kv.w*qv.w;
            nrm += kv.x*kv.x + kv.y*kv.y + kv.z*kv.z + kv.w*kv.w;
        }
        #pragma unroll
        for (int o = 16; o; o >>= 1) {
            dot += __shfl_down_sync(0xffffffffu, dot, o);
            nrm += __shfl_down_sync(0xffffffffu, nrm, o);
        }
        if (lane == 0) sim[w] = dot * rsqrtf(nrm);
    }
    __syncthreads();

    // ---- top-5, strict '>' = lowest index wins ties (matches jax.lax.top_k)
    if (t == 0) {
        unsigned usedmask = 0u;
        for (int k = 0; k < TOP_K; ++k) {
            int best = 0; float bv = -3.0e38f;
            #pragma unroll
            for (int p = 0; p < POOL_SIZE; ++p)
                if (!((usedmask >> p) & 1u) && sim[p] > bv) { bv = sim[p]; best = p; }
            usedmask |= 1u << best;
            idxs[k] = best;
        }
    }
    __syncthreads();

    // ---- one warp per token position l = w: gates + weighted sum
    const float ab0 = ab[0];
    const float4* rows[TOP_K];
    #pragma unroll
    for (int k = 0; k < TOP_K; ++k)
        rows[k] = pool4 + (idxs[k] * PROMPT_LEN + w) * EMBED_F4;

    float dots[TOP_K] = {0.f, 0.f, 0.f, 0.f, 0.f};
    #pragma unroll
    for (int i = 0; i < 6; ++i) {
        const int c = lane + i * 32;
        float4 av = aw_s[c];
        #pragma unroll
        for (int k = 0; k < TOP_K; ++k) {
            float4 rv = __ldg(&rows[k][c]);
            dots[k] += rv.x*av.x + rv.y*av.y + rv.z*av.z + rv.w*av.w;
        }
    }
    #pragma unroll
    for (int k = 0; k < TOP_K; ++k) {
        #pragma unroll
        for (int o = 16; o; o >>= 1)
            dots[k] += __shfl_xor_sync(0xffffffffu, dots[k], o);
    }
    float wt[TOP_K];
    #pragma unroll
    for (int k = 0; k < TOP_K; ++k)
        wt[k] = 1.f / (1.f + __expf(-(dots[k] + ab0)));

    #pragma unroll
    for (int i = 0; i < 6; ++i) {
        const int c = lane + i * 32;
        float4 acc = make_float4(0.f, 0.f, 0.f, 0.f);
        #pragma unroll
        for (int k = 0; k < TOP_K; ++k) {
            float4 rv = __ldg(&rows[k][c]);      // L1 hit
            acc.x += wt[k]*rv.x; acc.y += wt[k]*rv.y;
            acc.z += wt[k]*rv.z; acc.w += wt[k]*rv.w;
        }
        g_combined4[w * EMBED_F4 + c] = acc;
        cmb_s[w * EMBED_F4 + c] = acc;           // own smem copy for phase B
    }
}

// ---- phase A row dispatcher (ctx rows come from SMEM) ----
__device__ __forceinline__
void do_row_A(unsigned R, int lane,
              const float4* __restrict__ pre4,
              const float4* __restrict__ suf4,
              const float4* __restrict__ pool4,
              const float4* __restrict__ key4,
              const float4* __restrict__ ctx_s,
              float4* __restrict__ out)
{
    if (R < 45000u) {
        const unsigned c = R / 45u;            // magic-multiply
        const unsigned r = R - c * 45u;
        if (r == 0u) {
            copy_row_stream(pre4 + c * EMBED_F4, out + c * CLS_F4, lane);
        } else if (r <= 32u) {
            copy_row_smem(ctx_s + (r - 1u) * EMBED_F4,
                          out + c * CLS_F4 + (r + 32u) * EMBED_F4, lane);
        } else {
            copy_row_stream(suf4 + c * SUF_F4 + (r - 33u) * EMBED_F4,
                            out + c * CLS_F4 + (r + 32u) * EMBED_F4, lane);
        }
    } else {
        const unsigned q = R - 45000u;         // 0..1055: pool then key
        const float4* src = (q < 1024u) ? (pool4 + q * EMBED_F4)
                                        : (key4 + (q - 1024u) * EMBED_F4);
        copy_row_stream(src, out + PROMPTS_F4 + q * EMBED_F4, lane);
    }
}

// ============================================================
// The single persistent kernel (dynamic warp-level work queues)
// ============================================================
__global__ __launch_bounds__(BLOCK_X, 1)
void k_all(const float4* __restrict__ x4,
           const float4* __restrict__ key4,
           const float4* __restrict__ pool4,
           const float4* __restrict__ aw4,
           const float*  __restrict__ ab,
           const float4* __restrict__ pre4,
           const float4* __restrict__ suf4,
           const float4* __restrict__ ctx4,
           float4* __restrict__ out)
{
    extern __shared__ float4 dyn_s[];
    float4* __restrict__ ctx_s = dyn_s;            // [CTX_F4]
    float4* __restrict__ cmb_s = dyn_s + CTX_F4;   // [CMB_F4]

    __shared__ float4 qs4[EMBED_F4];
    __shared__ float4 aw_s[EMBED_F4];
    __shared__ float  sim[POOL_SIZE];
    __shared__ int    idxs[TOP_K];

    const int t = threadIdx.x;
    const int w = t >> 5, lane = t & 31;
    const unsigned b = blockIdx.x;
    const unsigned nb = gridDim.x;

    if (b == 0) {
        // ---- selection + gating + combined on a private SM, then release
        compute_combined(x4, key4, pool4, aw4, ab, cmb_s, qs4, aw_s, sim, idxs);
        __syncthreads();
        __threadfence();
        if (t == 0) atomicExch(&g_flag, 1);
    }

    // ---- stage ctx into SMEM: warp w loads row w (L2-hit for most blocks)
    {
        const float4* src = ctx4 + w * EMBED_F4;
        float4* dst = ctx_s + w * EMBED_F4;
        #pragma unroll
        for (int i = 0; i < 6; ++i) dst[lane + i * 32] = __ldg(&src[lane + i * 32]);
    }
    __syncthreads();

    // ---- Phase A: dynamic warp-level queue (prefetched atomic fetch)
    {
        unsigned base = 0u;
        if (lane == 0) base = atomicAdd(&g_qa, CHUNK);
        base = __shfl_sync(0xffffffffu, base, 0);
        while (base < NROWS_A) {
            unsigned nxt = 0u;
            if (lane == 0) nxt = atomicAdd(&g_qa, CHUNK);   // prefetch next chunk
            nxt = __shfl_sync(0xffffffffu, nxt, 0);
            unsigned end = base + CHUNK; if (end > NROWS_A) end = NROWS_A;
            for (unsigned R = base; R < end; ++R)
                do_row_A(R, lane, pre4, suf4, pool4, key4, ctx_s, out);
            base = nxt;
        }
    }

    if (b != 0) {
        // ---- wait for combined, then stage it into SMEM (src L2-hot)
        if (t == 0) {
            while (atomicAdd(&g_flag, 0) == 0) __nanosleep(64);
        }
        __syncthreads();
        __threadfence();
        {
            const float4* src = g_combined4 + w * EMBED_F4;
            float4* dst = cmb_s + w * EMBED_F4;
            #pragma unroll
            for (int i = 0; i < 6; ++i) dst[lane + i * 32] = __ldg(&src[lane + i * 32]);
        }
        __syncthreads();
    }
    // (block 0's cmb_s was filled during compute_combined, already synced)

    // ---- Phase B: dynamic queue; 32 combined rows -> 1000 classes, src SMEM
    {
        unsigned base = 0u;
        if (lane == 0) base = atomicAdd(&g_qb, CHUNK);
        base = __shfl_sync(0xffffffffu, base, 0);
        while (base < NROWS_B) {
            unsigned nxt = 0u;
            if (lane == 0) nxt = atomicAdd(&g_qb, CHUNK);
            nxt = __shfl_sync(0xffffffffu, nxt, 0);
            unsigned end = base + CHUNK; if (end > NROWS_B) end = NROWS_B;
            for (unsigned R = base; R < end; ++R) {
                const unsigned c = R >> 5;
                const unsigned r = R & 31u;
                copy_row_smem(cmb_s + r * EMBED_F4,
                              out + c * CLS_F4 + (r + 1u) * EMBED_F4, lane);
            }
            base = nxt;
        }
    }

    // ---- self-reset sync state so every graph replay starts clean
    __syncthreads();
    if (t == 0) {
        __threadfence();
        unsigned prev = atomicAdd(&g_done, 1u);
        if (prev == nb - 1u) {
            g_done = 0u; g_flag = 0; g_qa = 0u; g_qb = 0u;
        }
    }
}

// ============================================================
extern "C" void kernel_launch(void* const* d_in, const int* in_sizes, int n_in,
                              void* d_out, int out_size)
{
    const float* x_embed      = (const float*)d_in[0];
    const float* prompt_pool  = (const float*)d_in[1];
    const float* prompt_key   = (const float*)d_in[2];
    const float* alpha_w      = (const float*)d_in[3];
    const float* alpha_b      = (const float*)d_in[4];
    const float* ctx          = (const float*)d_in[5];
    const float* token_prefix = (const float*)d_in[6];
    const float* token_suffix = (const float*)d_in[7];
    // d_in[8] = train_flag: the penalty is a positive scalar on sims ->
    // top-k ordering (and therefore the output) is unchanged; safely ignored.

    static int attr_done = 0;
    if (!attr_done) {
        cudaFuncSetAttribute(k_all, cudaFuncAttributeMaxDynamicSharedMemorySize,
                             DYN_SMEM_BYTES);
        attr_done = 1;
    }

    k_all<<<GRID_X, BLOCK_X, DYN_SMEM_BYTES>>>(
        (const float4*)x_embed,
        (const float4*)prompt_key,
        (const float4*)prompt_pool,
        (const float4*)alpha_w,
        alpha_b,
        (const float4*)token_prefix,
        (const float4*)token_suffix,
        (const float4*)ctx,
        (float4*)d_out);
}

// round 9
// speedup vs baseline: 1.3173x; 1.2885x over previous
#include <cuda_runtime.h>
#include <cuda_bf16.h>

// -------- constants from the reference --------
#define POOL_SIZE   32
#define PROMPT_LEN  32
#define NCTX        32
#define EMBED       768
#define TOP_K       5
#define N_CLS       1000
#define SUFFIX_LEN  12
#define EMBED_F4    (EMBED / 4)          // 192
#define CLS_F4      14784u               // 77*192
#define PROMPTS_F4  14784000u            // 1000*14784
#define SUF_F4      2304u                // 12*192

// Phase A flat float4 space: 1000 classes x 45 rows x 192  +  pool/key
#define NA_PROMPT_F4  8640000u           // 1000*45*192
#define NA_TOTAL_F4   8842752u           // + 196608 + 6144
#define ROWS45_F4     8640u              // 45*192
// Phase B flat float4 space: 1000 classes x 32 rows x 192
#define NB_TOTAL_F4   6144000u
#define CMBCLS_F4     6144u              // 32*192

// -------- device scratch (no allocations allowed) --------
__device__ float4 g_combined4[PROMPT_LEN * EMBED_F4];

// ============================================================
// kAB: selection + gating + combined, ONE block, 1024 threads
// ============================================================
__global__ __launch_bounds__(1024, 1)
void kAB_fused(const float4* __restrict__ x4,       // [16,192]
               const float4* __restrict__ key4,     // [32,192]
               const float4* __restrict__ pool4,    // [32,32,192]
               const float4* __restrict__ aw4,      // [192]
               const float*  __restrict__ ab)       // [1]
{
    __shared__ float4 part[4][EMBED_F4];
    __shared__ float4 qs4[EMBED_F4];
    __shared__ float4 aw_s[EMBED_F4];
    __shared__ float  sim[POOL_SIZE];
    __shared__ int    idxs[TOP_K];

    const int t = threadIdx.x;
    const int w = t >> 5, lane = t & 31;

    // ---- partial q sums (mean scale & q-norm don't affect top-k ordering)
    if (t < 768) {
        const int grp = t / EMBED_F4;       // 0..3
        const int col = t - grp * EMBED_F4;
        float4 s = make_float4(0.f, 0.f, 0.f, 0.f);
        #pragma unroll
        for (int f = 0; f < 4; ++f) {
            float4 v = x4[(grp * 4 + f) * EMBED_F4 + col];
            s.x += v.x; s.y += v.y; s.z += v.z; s.w += v.w;
        }
        part[grp][col] = s;
    } else if (t < 768 + EMBED_F4) {
        aw_s[t - 768] = aw4[t - 768];
    }
    __syncthreads();
    if (t < EMBED_F4) {
        float4 a = part[0][t], b = part[1][t], c = part[2][t], d = part[3][t];
        qs4[t] = make_float4(a.x+b.x+c.x+d.x, a.y+b.y+c.y+d.y,
                             a.z+b.z+c.z+d.z, a.w+b.w+c.w+d.w);
    }
    __syncthreads();

    // ---- one warp per pool key: sim = (k.q)/||k|| (cosine-order equivalent)
    {
        const float4* kp = key4 + w * EMBED_F4;
        float dot = 0.f, nrm = 0.f;
        #pragma unroll
        for (int i = 0; i < 6; ++i) {
            const int c = lane + i * 32;
            float4 kv = kp[c], qv = qs4[c];
            dot += kv.x*qv.x + kv.y*qv.y + kv.z*qv.z + kv.w*qv.w;
            nrm += kv.x*kv.x + kv.y*kv.y + kv.z*kv.z + kv.w*kv.w;
        }
        #pragma unroll
        for (int o = 16; o; o >>= 1) {
            dot += __shfl_down_sync(0xffffffffu, dot, o);
            nrm += __shfl_down_sync(0xffffffffu, nrm, o);
        }
        if (lane == 0) sim[w] = dot * rsqrtf(nrm);
    }
    __syncthreads();

    // ---- top-5, strict '>' = lowest index wins ties (matches jax.lax.top_k)
    if (t == 0) {
        unsigned usedmask = 0u;
        for (int k = 0; k < TOP_K; ++k) {
            int best = 0; float bv = -3.0e38f;
            #pragma unroll
            for (int p = 0; p < POOL_SIZE; ++p)
                if (!((usedmask >> p) & 1u) && sim[p] > bv) { bv = sim[p]; best = p; }
            usedmask |= 1u << best;
            idxs[k] = best;
        }
    }
    __syncthreads();

    // ---- one warp per token position l = w: gates + weighted sum
    const float ab0 = ab[0];
    const float4* rows[TOP_K];
    #pragma unroll
    for (int k = 0; k < TOP_K; ++k)
        rows[k] = pool4 + (idxs[k] * PROMPT_LEN + w) * EMBED_F4;

    float dots[TOP_K] = {0.f, 0.f, 0.f, 0.f, 0.f};
    #pragma unroll
    for (int i = 0; i < 6; ++i) {
        const int c = lane + i * 32;
        float4 av = aw_s[c];
        #pragma unroll
        for (int k = 0; k < TOP_K; ++k) {
            float4 rv = rows[k][c];
            dots[k] += rv.x*av.x + rv.y*av.y + rv.z*av.z + rv.w*av.w;
        }
    }
    #pragma unroll
    for (int k = 0; k < TOP_K; ++k) {
        #pragma unroll
        for (int o = 16; o; o >>= 1)
            dots[k] += __shfl_xor_sync(0xffffffffu, dots[k], o);
    }
    float wt[TOP_K];
    #pragma unroll
    for (int k = 0; k < TOP_K; ++k)
        wt[k] = 1.f / (1.f + __expf(-(dots[k] + ab0)));

    #pragma unroll
    for (int i = 0; i < 6; ++i) {
        const int c = lane + i * 32;
        float4 acc = make_float4(0.f, 0.f, 0.f, 0.f);
        #pragma unroll
        for (int k = 0; k < TOP_K; ++k) {
            float4 rv = rows[k][c];               // L1 hit
            acc.x += wt[k]*rv.x; acc.y += wt[k]*rv.y;
            acc.z += wt[k]*rv.z; acc.w += wt[k]*rv.w;
        }
        g_combined4[w * EMBED_F4 + c] = acc;
    }
}

// ============================================================
// kC_A: selection-independent output (prefix, ctx, suffix, pool, key)
// ============================================================
__global__ void kC_A(const float4* __restrict__ pre4,
                     const float4* __restrict__ suf4,
                     const float4* __restrict__ ctx4,
                     const float4* __restrict__ pol4,
                     const float4* __restrict__ key4,
                     float4* __restrict__ out)
{
    unsigned idx = blockIdx.x * blockDim.x + threadIdx.x;
    const unsigned stride = gridDim.x * blockDim.x;

    for (; idx < NA_TOTAL_F4; idx += stride) {
        float4 v;
        unsigned o;
        if (idx < NA_PROMPT_F4) {
            const unsigned c   = idx / ROWS45_F4;        // magic-multiply
            const unsigned rem = idx - c * ROWS45_F4;
            const unsigned r   = rem / EMBED_F4;
            const unsigned col = rem - r * EMBED_F4;
            if (r == 0u) {
                v = __ldcs(&pre4[c * EMBED_F4 + col]);
                o = c * CLS_F4 + col;
            } else if (r <= 32u) {
                v = __ldg(&ctx4[(r - 1u) * EMBED_F4 + col]);   // reused 1000x
                o = c * CLS_F4 + (r + 32u) * EMBED_F4 + col;
            } else {
                v = __ldcs(&suf4[c * SUF_F4 + (r - 33u) * EMBED_F4 + col]);
                o = c * CLS_F4 + (r + 32u) * EMBED_F4 + col;
            }
        } else {
            const unsigned q = idx - NA_PROMPT_F4;       // pool then key
            v = (q < 196608u) ? __ldcs(&pol4[q]) : __ldcs(&key4[q - 196608u]);
            o = PROMPTS_F4 + q;
        }
        __stcs(&out[o], v);
    }
}

// ============================================================
// kC_B: broadcast the 32 combined rows to all 1000 classes
// ============================================================
__global__ void kC_B(float4* __restrict__ out)
{
    const float4* __restrict__ cmb4 = g_combined4;
    unsigned idx = blockIdx.x * blockDim.x + threadIdx.x;
    const unsigned stride = gridDim.x * blockDim.x;

    for (; idx < NB_TOTAL_F4; idx += stride) {
        const unsigned c   = idx / CMBCLS_F4;            // magic-multiply
        const unsigned rem = idx - c * CMBCLS_F4;
        __stcs(&out[c * CLS_F4 + EMBED_F4 + rem], __ldg(&cmb4[rem]));
    }
}

// ============================================================
extern "C" void kernel_launch(void* const* d_in, const int* in_sizes, int n_in,
                              void* d_out, int out_size)
{
    const float* x_embed      = (const float*)d_in[0];
    const float* prompt_pool  = (const float*)d_in[1];
    const float* prompt_key   = (const float*)d_in[2];
    const float* alpha_w      = (const float*)d_in[3];
    const float* alpha_b      = (const float*)d_in[4];
    const float* ctx          = (const float*)d_in[5];
    const float* token_prefix = (const float*)d_in[6];
    const float* token_suffix = (const float*)d_in[7];
    // d_in[8] = train_flag: the penalty is a positive scalar on sims ->
    // top-k ordering (and therefore the output) is unchanged; safely ignored.

    // Side stream + fork/join events, created once on the first (non-capture)
    // correctness call. No device memory is allocated.
    static cudaStream_t s1;
    static cudaEvent_t  eFork, eJoin;
    static int init = 0;
    if (!init) {
        cudaStreamCreateWithFlags(&s1, cudaStreamNonBlocking);
        cudaEventCreateWithFlags(&eFork, cudaEventDisableTiming);
        cudaEventCreateWithFlags(&eJoin, cudaEventDisableTiming);
        init = 1;
    }

    // fork: side branch waits on the capture stream's front
    cudaEventRecord(eFork, 0);
    cudaStreamWaitEvent(s1, eFork, 0);

    // branch 1: selection compute, then the dependent broadcast region
    kAB_fused<<<1, 1024, 0, s1>>>((const float4*)x_embed,
                                  (const float4*)prompt_key,
                                  (const float4*)prompt_pool,
                                  (const float4*)alpha_w,
                                  alpha_b);
    kC_B<<<3000, 256, 0, s1>>>((float4*)d_out);

    // branch 0: everything independent of the selection (runs concurrently)
    kC_A<<<4318, 256>>>((const float4*)token_prefix,
                        (const float4*)token_suffix,
                        (const float4*)ctx,
                        (const float4*)prompt_pool,
                        (const float4*)prompt_key,
                        (float4*)d_out);

    // join: capture stream waits for the side branch
    cudaEventRecord(eJoin, s1);
    cudaStreamWaitEvent(0, eJoin, 0);
}

// round 10
// speedup vs baseline: 1.3473x; 1.0227x over previous
#include <cuda_runtime.h>
#include <cuda_bf16.h>

// -------- constants from the reference --------
#define POOL_SIZE   32
#define PROMPT_LEN  32
#define NCTX        32
#define EMBED       768
#define TOP_K       5
#define N_CLS       1000
#define SUFFIX_LEN  12
#define EMBED_F4    (EMBED / 4)          // 192
#define CLS_F4      14784u               // 77*192
#define PROMPTS_F4  14784000u            // 1000*14784
#define SUF_F4      2304u                // 12*192

// Phase A flat float4 space: 1000 classes x 45 rows x 192  +  pool/key
#define NA_PROMPT_F4  8640000u           // 1000*45*192
#define NA_TOTAL_F4   8842752u           // + 196608 + 6144
#define ROWS45_F4     8640u              // 45*192
// Phase B flat float4 space: 1000 classes x 32 rows x 192
#define NB_TOTAL_F4   6144000u
#define CMBCLS_F4     6144u              // 32*192

// -------- device scratch (no allocations allowed) --------
__device__ float  g_sim[POOL_SIZE];
__device__ float4 g_combined4[PROMPT_LEN * EMBED_F4];

// ============================================================
// kSim: one block per pool key (32 blocks x 192 threads).
// Each block redundantly computes q (x is L2-shared) and its key's
// sim = (k.q)/||k||  (order-equivalent to cosine similarity).
// ============================================================
__global__ __launch_bounds__(192, 1)
void kSim(const float4* __restrict__ x4,       // [16,192]
          const float4* __restrict__ key4)     // [32,192]
{
    __shared__ float sdot[6], snrm[6];
    const int t = threadIdx.x;                 // 0..191 (one f4 column each)
    const int w = t >> 5, lane = t & 31;
    const int p = blockIdx.x;

    // q column = sum over 16 frames (mean scale & q-norm don't affect top-k)
    float4 q = make_float4(0.f, 0.f, 0.f, 0.f);
    #pragma unroll
    for (int f = 0; f < 16; ++f) {
        float4 v = __ldg(&x4[f * EMBED_F4 + t]);
        q.x += v.x; q.y += v.y; q.z += v.z; q.w += v.w;
    }
    float4 kv = __ldg(&key4[p * EMBED_F4 + t]);
    float dot = kv.x*q.x + kv.y*q.y + kv.z*q.z + kv.w*q.w;
    float nrm = kv.x*kv.x + kv.y*kv.y + kv.z*kv.z + kv.w*kv.w;

    #pragma unroll
    for (int o = 16; o; o >>= 1) {
        dot += __shfl_down_sync(0xffffffffu, dot, o);
        nrm += __shfl_down_sync(0xffffffffu, nrm, o);
    }
    if (lane == 0) { sdot[w] = dot; snrm[w] = nrm; }
    __syncthreads();
    if (t == 0) {
        float d = 0.f, n = 0.f;
        #pragma unroll
        for (int i = 0; i < 6; ++i) { d += sdot[i]; n += snrm[i]; }
        g_sim[p] = d * rsqrtf(n);
    }
}

// ============================================================
// kGate: one block per token position (32 blocks x 192 threads).
// Redundant top-5 per block (32 values, trivial), then gates + weighted sum.
// ============================================================
__global__ __launch_bounds__(192, 1)
void kGate(const float4* __restrict__ pool4,   // [32,32,192]
           const float4* __restrict__ aw4,     // [192]
           const float*  __restrict__ ab)      // [1]
{
    __shared__ float sims[POOL_SIZE];
    __shared__ int   idxs[TOP_K];
    __shared__ float part[6][TOP_K];
    __shared__ float wt_s[TOP_K];

    const int t = threadIdx.x;                 // one f4 column each
    const int w = t >> 5, lane = t & 31;
    const int l = blockIdx.x;

    if (t < POOL_SIZE) sims[t] = g_sim[t];
    __syncthreads();

    // top-5, strict '>' = lowest index wins ties (matches jax.lax.top_k)
    if (t == 0) {
        unsigned usedmask = 0u;
        for (int k = 0; k < TOP_K; ++k) {
            int best = 0; float bv = -3.0e38f;
            #pragma unroll
            for (int p = 0; p < POOL_SIZE; ++p)
                if (!((usedmask >> p) & 1u) && sims[p] > bv) { bv = sims[p]; best = p; }
            usedmask |= 1u << best;
            idxs[k] = best;
        }
    }
    __syncthreads();

    const float4* rows[TOP_K];
    #pragma unroll
    for (int k = 0; k < TOP_K; ++k)
        rows[k] = pool4 + (idxs[k] * PROMPT_LEN + l) * EMBED_F4;

    // gate dots: each thread handles its column for all 5 selections
    float4 av = __ldg(&aw4[t]);
    float4 rv[TOP_K];
    float dots[TOP_K];
    #pragma unroll
    for (int k = 0; k < TOP_K; ++k) {
        rv[k] = __ldg(&rows[k][t]);
        dots[k] = rv[k].x*av.x + rv[k].y*av.y + rv[k].z*av.z + rv[k].w*av.w;
    }
    #pragma unroll
    for (int k = 0; k < TOP_K; ++k) {
        #pragma unroll
        for (int o = 16; o; o >>= 1)
            dots[k] += __shfl_down_sync(0xffffffffu, dots[k], o);
    }
    if (lane == 0) {
        #pragma unroll
        for (int k = 0; k < TOP_K; ++k) part[w][k] = dots[k];
    }
    __syncthreads();
    if (t < TOP_K) {
        float d = 0.f;
        #pragma unroll
        for (int i = 0; i < 6; ++i) d += part[i][t];
        wt_s[t] = 1.f / (1.f + __expf(-(d + ab[0])));
    }
    __syncthreads();

    // combined row l: weighted sum over the 5 selected rows (rv in registers)
    float4 acc = make_float4(0.f, 0.f, 0.f, 0.f);
    #pragma unroll
    for (int k = 0; k < TOP_K; ++k) {
        const float wk = wt_s[k];
        acc.x += wk*rv[k].x; acc.y += wk*rv[k].y;
        acc.z += wk*rv[k].z; acc.w += wk*rv[k].w;
    }
    g_combined4[l * EMBED_F4 + t] = acc;
}

// ============================================================
// kC_A: selection-independent output (prefix, ctx, suffix, pool, key)
// ============================================================
__global__ void kC_A(const float4* __restrict__ pre4,
                     const float4* __restrict__ suf4,
                     const float4* __restrict__ ctx4,
                     const float4* __restrict__ pol4,
                     const float4* __restrict__ key4,
                     float4* __restrict__ out)
{
    unsigned idx = blockIdx.x * blockDim.x + threadIdx.x;
    const unsigned stride = gridDim.x * blockDim.x;

    for (; idx < NA_TOTAL_F4; idx += stride) {
        float4 v;
        unsigned o;
        if (idx < NA_PROMPT_F4) {
            const unsigned c   = idx / ROWS45_F4;        // magic-multiply
            const unsigned rem = idx - c * ROWS45_F4;
            const unsigned r   = rem / EMBED_F4;
            const unsigned col = rem - r * EMBED_F4;
            if (r == 0u) {
                v = __ldcs(&pre4[c * EMBED_F4 + col]);
                o = c * CLS_F4 + col;
            } else if (r <= 32u) {
                v = __ldg(&ctx4[(r - 1u) * EMBED_F4 + col]);   // reused 1000x
                o = c * CLS_F4 + (r + 32u) * EMBED_F4 + col;
            } else {
                v = __ldcs(&suf4[c * SUF_F4 + (r - 33u) * EMBED_F4 + col]);
                o = c * CLS_F4 + (r + 32u) * EMBED_F4 + col;
            }
        } else {
            const unsigned q = idx - NA_PROMPT_F4;       // pool then key
            v = (q < 196608u) ? __ldcs(&pol4[q]) : __ldcs(&key4[q - 196608u]);
            o = PROMPTS_F4 + q;
        }
        __stcs(&out[o], v);
    }
}

// ============================================================
// kC_B: broadcast the 32 combined rows to all 1000 classes
// ============================================================
__global__ void kC_B(float4* __restrict__ out)
{
    const float4* __restrict__ cmb4 = g_combined4;
    unsigned idx = blockIdx.x * blockDim.x + threadIdx.x;
    const unsigned stride = gridDim.x * blockDim.x;

    for (; idx < NB_TOTAL_F4; idx += stride) {
        const unsigned c   = idx / CMBCLS_F4;            // magic-multiply
        const unsigned rem = idx - c * CMBCLS_F4;
        __stcs(&out[c * CLS_F4 + EMBED_F4 + rem], __ldg(&cmb4[rem]));
    }
}

// ============================================================
extern "C" void kernel_launch(void* const* d_in, const int* in_sizes, int n_in,
                              void* d_out, int out_size)
{
    const float* x_embed      = (const float*)d_in[0];
    const float* prompt_pool  = (const float*)d_in[1];
    const float* prompt_key   = (const float*)d_in[2];
    const float* alpha_w      = (const float*)d_in[3];
    const float* alpha_b      = (const float*)d_in[4];
    const float* ctx          = (const float*)d_in[5];
    const float* token_prefix = (const float*)d_in[6];
    const float* token_suffix = (const float*)d_in[7];
    // d_in[8] = train_flag: the penalty is a positive scalar on sims ->
    // top-k ordering (and therefore the output) is unchanged; safely ignored.

    // Side stream + fork/join events, created once on the first (non-capture)
    // correctness call. No device memory is allocated.
    static cudaStream_t s1;
    static cudaEvent_t  eFork, eJoin;
    static int init = 0;
    if (!init) {
        cudaStreamCreateWithFlags(&s1, cudaStreamNonBlocking);
        cudaEventCreateWithFlags(&eFork, cudaEventDisableTiming);
        cudaEventCreateWithFlags(&eJoin, cudaEventDisableTiming);
        init = 1;
    }

    // fork: side branch waits on the capture stream's front
    cudaEventRecord(eFork, 0);
    cudaStreamWaitEvent(s1, eFork, 0);

    // branch 1 (side stream): multi-block selection chain, then broadcast
    kSim<<<POOL_SIZE, 192, 0, s1>>>((const float4*)x_embed,
                                    (const float4*)prompt_key);
    kGate<<<PROMPT_LEN, 192, 0, s1>>>((const float4*)prompt_pool,
                                      (const float4*)alpha_w, alpha_b);
    kC_B<<<3000, 256, 0, s1>>>((float4*)d_out);

    // branch 0 (capture stream): everything independent of the selection
    kC_A<<<4318, 256>>>((const float4*)token_prefix,
                        (const float4*)token_suffix,
                        (const float4*)ctx,
                        (const float4*)prompt_pool,
                        (const float4*)prompt_key,
                        (float4*)d_out);

    // join: capture stream waits for the side branch
    cudaEventRecord(eJoin, s1);
    cudaStreamWaitEvent(0, eJoin, 0);
}

// round 11
// speedup vs baseline: 1.4169x; 1.0517x over previous
#include <cuda_runtime.h>
#include <cuda_bf16.h>

// -------- constants from the reference --------
#define POOL_SIZE   32
#define PROMPT_LEN  32
#define NCTX        32
#define EMBED       768
#define TOP_K       5
#define N_CLS       1000
#define SUFFIX_LEN  12
#define EMBED_F4    (EMBED / 4)          // 192
#define CLS_F4      14784u               // 77*192
#define PROMPTS_F4  14784000u            // 1000*14784
#define SUF_F4      2304u                // 12*192

// Phase A flat float4 space: 1000 classes x 45 rows x 192  +  pool/key
#define NA_PROMPT_F4  8640000u           // 1000*45*192
#define NA_TOTAL_F4   8842752u           // + 196608 + 6144
#define ROWS45_F4     8640u              // 45*192
// Phase B flat float4 space: 1000 classes x 32 rows x 192
#define NB_TOTAL_F4   6144000u
#define CMBCLS_F4     6144u              // 32*192

// -------- device scratch / sync (zero-init at load) --------
__device__ float    g_sim[POOL_SIZE];
__device__ float4   g_combined4[PROMPT_LEN * EMBED_F4];
__device__ unsigned g_simdone;
__device__ unsigned g_seldone;

// ============================================================
// kSel: ONE kernel, 32 blocks x 192 threads.
// Block b: (1) sim for key b (redundant q-sum; x is L2-shared),
//          (2) spin until all 32 sims published (all blocks co-resident),
//          (3) redundant top-5, (4) gate + weighted sum for position b.
// ============================================================
__global__ __launch_bounds__(192, 1)
void kSel(const float4* __restrict__ x4,       // [16,192]
          const float4* __restrict__ key4,     // [32,192]
          const float4* __restrict__ pool4,    // [32,32,192]
          const float4* __restrict__ aw4,      // [192]
          const float*  __restrict__ ab)       // [1]
{
    __shared__ float sdot[6], snrm[6];
    __shared__ float sims[POOL_SIZE];
    __shared__ int   idxs[TOP_K];
    __shared__ float part[6][TOP_K];
    __shared__ float wt_s[TOP_K];

    const int t = threadIdx.x;                 // 0..191, one f4 column each
    const int w = t >> 5, lane = t & 31;
    const int b = blockIdx.x;                  // = key index = token position

    // ---- (1) sim_b = (k_b . q)/||k_b||  (cosine-order equivalent;
    //      mean scale & q-norm are positive scalars -> ordering unchanged)
    float4 q = make_float4(0.f, 0.f, 0.f, 0.f);
    #pragma unroll
    for (int f = 0; f < 16; ++f) {
        float4 v = __ldg(&x4[f * EMBED_F4 + t]);
        q.x += v.x; q.y += v.y; q.z += v.z; q.w += v.w;
    }
    float4 kv = __ldg(&key4[b * EMBED_F4 + t]);
    float dot = kv.x*q.x + kv.y*q.y + kv.z*q.z + kv.w*q.w;
    float nrm = kv.x*kv.x + kv.y*kv.y + kv.z*kv.z + kv.w*kv.w;
    #pragma unroll
    for (int o = 16; o; o >>= 1) {
        dot += __shfl_down_sync(0xffffffffu, dot, o);
        nrm += __shfl_down_sync(0xffffffffu, nrm, o);
    }
    if (lane == 0) { sdot[w] = dot; snrm[w] = nrm; }
    __syncthreads();
    if (t == 0) {
        float d = 0.f, n = 0.f;
        #pragma unroll
        for (int i = 0; i < 6; ++i) { d += sdot[i]; n += snrm[i]; }
        g_sim[b] = d * rsqrtf(n);
        __threadfence();
        atomicAdd(&g_simdone, 1u);
        // ---- (2) wait for all 32 sims (all 32 blocks are co-resident)
        while (atomicAdd(&g_simdone, 0) < POOL_SIZE) { }
    }
    __syncthreads();
    __threadfence();

    if (t < POOL_SIZE) sims[t] = g_sim[t];
    __syncthreads();

    // ---- (3) top-5, strict '>' = lowest index wins ties (jax.lax.top_k)
    if (t == 0) {
        unsigned usedmask = 0u;
        for (int k = 0; k < TOP_K; ++k) {
            int best = 0; float bv = -3.0e38f;
            #pragma unroll
            for (int p = 0; p < POOL_SIZE; ++p)
                if (!((usedmask >> p) & 1u) && sims[p] > bv) { bv = sims[p]; best = p; }
            usedmask |= 1u << best;
            idxs[k] = best;
        }
    }
    __syncthreads();

    // ---- (4) gates + weighted sum for token position l = b
    const float4* rows[TOP_K];
    #pragma unroll
    for (int k = 0; k < TOP_K; ++k)
        rows[k] = pool4 + (idxs[k] * PROMPT_LEN + b) * EMBED_F4;

    float4 av = __ldg(&aw4[t]);
    float4 rv[TOP_K];
    float dots[TOP_K];
    #pragma unroll
    for (int k = 0; k < TOP_K; ++k) {
        rv[k] = __ldg(&rows[k][t]);
        dots[k] = rv[k].x*av.x + rv[k].y*av.y + rv[k].z*av.z + rv[k].w*av.w;
    }
    #pragma unroll
    for (int k = 0; k < TOP_K; ++k) {
        #pragma unroll
        for (int o = 16; o; o >>= 1)
            dots[k] += __shfl_down_sync(0xffffffffu, dots[k], o);
    }
    if (lane == 0) {
        #pragma unroll
        for (int k = 0; k < TOP_K; ++k) part[w][k] = dots[k];
    }
    __syncthreads();
    if (t < TOP_K) {
        float d = 0.f;
        #pragma unroll
        for (int i = 0; i < 6; ++i) d += part[i][t];
        wt_s[t] = 1.f / (1.f + __expf(-(d + ab[0])));
    }
    __syncthreads();

    float4 acc = make_float4(0.f, 0.f, 0.f, 0.f);
    #pragma unroll
    for (int k = 0; k < TOP_K; ++k) {
        const float wk = wt_s[k];
        acc.x += wk*rv[k].x; acc.y += wk*rv[k].y;
        acc.z += wk*rv[k].z; acc.w += wk*rv[k].w;
    }
    g_combined4[b * EMBED_F4 + t] = acc;

    // ---- self-reset for graph replay (last block zeroes the counters)
    __syncthreads();
    if (t == 0) {
        __threadfence();
        unsigned prev = atomicAdd(&g_seldone, 1u);
        if (prev == POOL_SIZE - 1u) { g_simdone = 0u; g_seldone = 0u; }
    }
}

// ============================================================
// kC_A: selection-independent output (prefix, ctx, suffix, pool, key)
// ============================================================
__global__ void kC_A(const float4* __restrict__ pre4,
                     const float4* __restrict__ suf4,
                     const float4* __restrict__ ctx4,
                     const float4* __restrict__ pol4,
                     const float4* __restrict__ key4,
                     float4* __restrict__ out)
{
    unsigned idx = blockIdx.x * blockDim.x + threadIdx.x;
    const unsigned stride = gridDim.x * blockDim.x;

    for (; idx < NA_TOTAL_F4; idx += stride) {
        float4 v;
        unsigned o;
        if (idx < NA_PROMPT_F4) {
            const unsigned c   = idx / ROWS45_F4;        // magic-multiply
            const unsigned rem = idx - c * ROWS45_F4;
            const unsigned r   = rem / EMBED_F4;
            const unsigned col = rem - r * EMBED_F4;
            if (r == 0u) {
                v = __ldcs(&pre4[c * EMBED_F4 + col]);
                o = c * CLS_F4 + col;
            } else if (r <= 32u) {
                v = __ldg(&ctx4[(r - 1u) * EMBED_F4 + col]);   // reused 1000x
                o = c * CLS_F4 + (r + 32u) * EMBED_F4 + col;
            } else {
                v = __ldcs(&suf4[c * SUF_F4 + (r - 33u) * EMBED_F4 + col]);
                o = c * CLS_F4 + (r + 32u) * EMBED_F4 + col;
            }
        } else {
            const unsigned q = idx - NA_PROMPT_F4;       // pool then key
            v = (q < 196608u) ? __ldcs(&pol4[q]) : __ldcs(&key4[q - 196608u]);
            o = PROMPTS_F4 + q;
        }
        __stcs(&out[o], v);
    }
}

// ============================================================
// kC_B: broadcast the 32 combined rows to all 1000 classes
// ============================================================
__global__ void kC_B(float4* __restrict__ out)
{
    const float4* __restrict__ cmb4 = g_combined4;
    unsigned idx = blockIdx.x * blockDim.x + threadIdx.x;
    const unsigned stride = gridDim.x * blockDim.x;

    for (; idx < NB_TOTAL_F4; idx += stride) {
        const unsigned c   = idx / CMBCLS_F4;            // magic-multiply
        const unsigned rem = idx - c * CMBCLS_F4;
        __stcs(&out[c * CLS_F4 + EMBED_F4 + rem], __ldg(&cmb4[rem]));
    }
}

// ============================================================
extern "C" void kernel_launch(void* const* d_in, const int* in_sizes, int n_in,
                              void* d_out, int out_size)
{
    const float* x_embed      = (const float*)d_in[0];
    const float* prompt_pool  = (const float*)d_in[1];
    const float* prompt_key   = (const float*)d_in[2];
    const float* alpha_w      = (const float*)d_in[3];
    const float* alpha_b      = (const float*)d_in[4];
    const float* ctx          = (const float*)d_in[5];
    const float* token_prefix = (const float*)d_in[6];
    const float* token_suffix = (const float*)d_in[7];
    // d_in[8] = train_flag: the penalty is a positive scalar on sims ->
    // top-k ordering (and therefore the output) is unchanged; safely ignored.

    // Side stream + fork/join events, created once on the first (non-capture)
    // correctness call. No device memory is allocated.
    static cudaStream_t s1;
    static cudaEvent_t  eFork, eJoin;
    static int init = 0;
    if (!init) {
        cudaStreamCreateWithFlags(&s1, cudaStreamNonBlocking);
        cudaEventCreateWithFlags(&eFork, cudaEventDisableTiming);
        cudaEventCreateWithFlags(&eJoin, cudaEventDisableTiming);
        init = 1;
    }

    // fork: side branch waits on the capture stream's front
    cudaEventRecord(eFork, 0);
    cudaStreamWaitEvent(s1, eFork, 0);

    // branch 1 (side stream): single selection kernel, then broadcast
    kSel<<<POOL_SIZE, 192, 0, s1>>>((const float4*)x_embed,
                                    (const float4*)prompt_key,
                                    (const float4*)prompt_pool,
                                    (const float4*)alpha_w, alpha_b);
    kC_B<<<3000, 256, 0, s1>>>((float4*)d_out);

    // branch 0 (capture stream): everything independent of the selection
    kC_A<<<4318, 256>>>((const float4*)token_prefix,
                        (const float4*)token_suffix,
                        (const float4*)ctx,
                        (const float4*)prompt_pool,
                        (const float4*)prompt_key,
                        (float4*)d_out);

    // join: capture stream waits for the side branch
    cudaEventRecord(eJoin, s1);
    cudaStreamWaitEvent(0, eJoin, 0);
}

// round 12
// speedup vs baseline: 1.4179x; 1.0006x over previous
#include <cuda_runtime.h>
#include <cuda_bf16.h>

// -------- constants from the reference --------
#define POOL_SIZE   32
#define PROMPT_LEN  32
#define NCTX        32
#define EMBED       768
#define TOP_K       5
#define N_CLS       1000
#define SUFFIX_LEN  12
#define EMBED_F4    (EMBED / 4)          // 192
#define CLS_F4      14784u               // 77*192
#define PROMPTS_F4  14784000u            // 1000*14784
#define SUF_F4      2304u                // 12*192

// Phase A flat float4 space: 1000 classes x 45 rows x 192  +  pool/key
#define NA_PROMPT_F4  8640000u           // 1000*45*192
#define NA_TOTAL_F4   8842752u           // + 196608 + 6144
#define ROWS45_F4     8640u              // 45*192
// Phase B flat float4 space: 1000 classes x 32 rows x 192
#define NB_TOTAL_F4   6144000u
#define CMBCLS_F4     6144u              // 32*192

// -------- device scratch (zero-init at load) --------
__device__ float4 g_combined4[PROMPT_LEN * EMBED_F4];

// ============================================================
// kSel: 32 independent blocks x 256 threads, NO inter-block sync.
// Block b: prefetch all 32 candidate pool rows for position b into L2,
// redundantly compute ALL 32 sims (x/keys are L2-shared), top-5,
// then gates + weighted sum for token position b.
// ============================================================
__global__ __launch_bounds__(256, 1)
void kSel(const float4* __restrict__ x4,       // [16,192]
          const float4* __restrict__ key4,     // [32,192]
          const float4* __restrict__ pool4,    // [32,32,192]
          const float4* __restrict__ aw4,      // [192]
          const float*  __restrict__ ab)       // [1]
{
    __shared__ float4 qs4[EMBED_F4];
    __shared__ float  sims[POOL_SIZE];
    __shared__ int    idxs[TOP_K];
    __shared__ float  part[6][TOP_K];
    __shared__ float  wt_s[TOP_K];

    const int t = threadIdx.x;
    const int w = t >> 5, lane = t & 31;
    const int b = blockIdx.x;                  // token position (and nothing else)

    // ---- L2-prefetch the 32 candidate pool rows for position b
    //      (row = pool4 + (p*PROMPT_LEN + b)*EMBED_F4; 24 lines of 128B each)
    for (int i = t; i < 32 * 24; i += 256) {
        const int p = i / 24, line = i - p * 24;
        const float4* addr = pool4 + (p * PROMPT_LEN + b) * EMBED_F4 + line * 8;
        asm volatile("prefetch.global.L2 [%0];" :: "l"(addr));
    }

    // ---- q = sum over 16 frames (mean scale & q-norm don't affect top-k)
    if (t < EMBED_F4) {
        float4 s = make_float4(0.f, 0.f, 0.f, 0.f);
        #pragma unroll
        for (int f = 0; f < 16; ++f) {
            float4 v = __ldg(&x4[f * EMBED_F4 + t]);
            s.x += v.x; s.y += v.y; s.z += v.z; s.w += v.w;
        }
        qs4[t] = s;
    }
    __syncthreads();

    // ---- ALL 32 sims, redundantly per block: 8 warps x 4 keys
    //      sim = (k.q)/||k||  (order-equivalent to cosine similarity)
    #pragma unroll
    for (int j = 0; j < 4; ++j) {
        const int p = w + 8 * j;
        const float4* kp = key4 + p * EMBED_F4;
        float dot = 0.f, nrm = 0.f;
        #pragma unroll
        for (int i = 0; i < 6; ++i) {
            const int c = lane + i * 32;
            float4 kv = __ldg(&kp[c]), qv = qs4[c];
            dot += kv.x*qv.x + kv.y*qv.y + kv.z*qv.z + kv.w*qv.w;
            nrm += kv.x*kv.x + kv.y*kv.y + kv.z*kv.z + kv.w*kv.w;
        }
        #pragma unroll
        for (int o = 16; o; o >>= 1) {
            dot += __shfl_down_sync(0xffffffffu, dot, o);
            nrm += __shfl_down_sync(0xffffffffu, nrm, o);
        }
        if (lane == 0) sims[p] = dot * rsqrtf(nrm);
    }
    __syncthreads();

    // ---- top-5, strict '>' = lowest index wins ties (matches jax.lax.top_k)
    if (t == 0) {
        unsigned usedmask = 0u;
        for (int k = 0; k < TOP_K; ++k) {
            int best = 0; float bv = -3.0e38f;
            #pragma unroll
            for (int p = 0; p < POOL_SIZE; ++p)
                if (!((usedmask >> p) & 1u) && sims[p] > bv) { bv = sims[p]; best = p; }
            usedmask |= 1u << best;
            idxs[k] = best;
        }
    }
    __syncthreads();

    // ---- gates + weighted sum for token position b (first 192 threads)
    if (t < EMBED_F4) {
        const float4* rows[TOP_K];
        #pragma unroll
        for (int k = 0; k < TOP_K; ++k)
            rows[k] = pool4 + (idxs[k] * PROMPT_LEN + b) * EMBED_F4;

        float4 av = __ldg(&aw4[t]);
        float4 rv[TOP_K];
        float dots[TOP_K];
        #pragma unroll
        for (int k = 0; k < TOP_K; ++k) {
            rv[k] = __ldg(&rows[k][t]);          // L2 hit (prefetched)
            dots[k] = rv[k].x*av.x + rv[k].y*av.y + rv[k].z*av.z + rv[k].w*av.w;
        }
        #pragma unroll
        for (int k = 0; k < TOP_K; ++k) {
            #pragma unroll
            for (int o = 16; o; o >>= 1)
                dots[k] += __shfl_down_sync(0xffffffffu, dots[k], o);
        }
        if (lane == 0) {
            #pragma unroll
            for (int k = 0; k < TOP_K; ++k) part[w][k] = dots[k];
        }
        __syncthreads();
        if (t < TOP_K) {
            float d = 0.f;
            #pragma unroll
            for (int i = 0; i < 6; ++i) d += part[i][t];
            wt_s[t] = 1.f / (1.f + __expf(-(d + ab[0])));
        }
        __syncthreads();

        float4 acc = make_float4(0.f, 0.f, 0.f, 0.f);
        #pragma unroll
        for (int k = 0; k < TOP_K; ++k) {
            const float wk = wt_s[k];
            acc.x += wk*rv[k].x; acc.y += wk*rv[k].y;
            acc.z += wk*rv[k].z; acc.w += wk*rv[k].w;
        }
        g_combined4[b * EMBED_F4 + t] = acc;
    } else {
        // keep barrier participation symmetric
        __syncthreads();
        __syncthreads();
    }
}

// ============================================================
// kC_A: selection-independent output (prefix, ctx, suffix, pool, key)
// ============================================================
__global__ void kC_A(const float4* __restrict__ pre4,
                     const float4* __restrict__ suf4,
                     const float4* __restrict__ ctx4,
                     const float4* __restrict__ pol4,
                     const float4* __restrict__ key4,
                     float4* __restrict__ out)
{
    unsigned idx = blockIdx.x * blockDim.x + threadIdx.x;
    const unsigned stride = gridDim.x * blockDim.x;

    for (; idx < NA_TOTAL_F4; idx += stride) {
        float4 v;
        unsigned o;
        if (idx < NA_PROMPT_F4) {
            const unsigned c   = idx / ROWS45_F4;        // magic-multiply
            const unsigned rem = idx - c * ROWS45_F4;
            const unsigned r   = rem / EMBED_F4;
            const unsigned col = rem - r * EMBED_F4;
            if (r == 0u) {
                v = __ldcs(&pre4[c * EMBED_F4 + col]);
                o = c * CLS_F4 + col;
            } else if (r <= 32u) {
                v = __ldg(&ctx4[(r - 1u) * EMBED_F4 + col]);   // reused 1000x
                o = c * CLS_F4 + (r + 32u) * EMBED_F4 + col;
            } else {
                v = __ldcs(&suf4[c * SUF_F4 + (r - 33u) * EMBED_F4 + col]);
                o = c * CLS_F4 + (r + 32u) * EMBED_F4 + col;
            }
        } else {
            const unsigned q = idx - NA_PROMPT_F4;       // pool then key
            v = (q < 196608u) ? __ldcs(&pol4[q]) : __ldcs(&key4[q - 196608u]);
            o = PROMPTS_F4 + q;
        }
        __stcs(&out[o], v);
    }
}

// ============================================================
// kC_B: broadcast the 32 combined rows to all 1000 classes
// ============================================================
__global__ void kC_B(float4* __restrict__ out)
{
    const float4* __restrict__ cmb4 = g_combined4;
    unsigned idx = blockIdx.x * blockDim.x + threadIdx.x;
    const unsigned stride = gridDim.x * blockDim.x;

    for (; idx < NB_TOTAL_F4; idx += stride) {
        const unsigned c   = idx / CMBCLS_F4;            // magic-multiply
        const unsigned rem = idx - c * CMBCLS_F4;
        __stcs(&out[c * CLS_F4 + EMBED_F4 + rem], __ldg(&cmb4[rem]));
    }
}

// ============================================================
extern "C" void kernel_launch(void* const* d_in, const int* in_sizes, int n_in,
                              void* d_out, int out_size)
{
    const float* x_embed      = (const float*)d_in[0];
    const float* prompt_pool  = (const float*)d_in[1];
    const float* prompt_key   = (const float*)d_in[2];
    const float* alpha_w      = (const float*)d_in[3];
    const float* alpha_b      = (const float*)d_in[4];
    const float* ctx          = (const float*)d_in[5];
    const float* token_prefix = (const float*)d_in[6];
    const float* token_suffix = (const float*)d_in[7];
    // d_in[8] = train_flag: the penalty is a positive scalar on sims ->
    // top-k ordering (and therefore the output) is unchanged; safely ignored.

    // Side stream + fork/join events, created once on the first (non-capture)
    // correctness call. No device memory is allocated.
    static cudaStream_t s1;
    static cudaEvent_t  eFork, eJoin;
    static int init = 0;
    if (!init) {
        cudaStreamCreateWithFlags(&s1, cudaStreamNonBlocking);
        cudaEventCreateWithFlags(&eFork, cudaEventDisableTiming);
        cudaEventCreateWithFlags(&eJoin, cudaEventDisableTiming);
        init = 1;
    }

    // fork: side branch waits on the capture stream's front
    cudaEventRecord(eFork, 0);
    cudaStreamWaitEvent(s1, eFork, 0);

    // branch 1 (side stream): independent-block selection, then broadcast
    kSel<<<POOL_SIZE, 256, 0, s1>>>((const float4*)x_embed,
                                    (const float4*)prompt_key,
                                    (const float4*)prompt_pool,
                                    (const float4*)alpha_w, alpha_b);
    kC_B<<<3000, 256, 0, s1>>>((float4*)d_out);

    // branch 0 (capture stream): everything independent of the selection
    kC_A<<<4318, 256>>>((const float4*)token_prefix,
                        (const float4*)token_suffix,
                        (const float4*)ctx,
                        (const float4*)prompt_pool,
                        (const float4*)prompt_key,
                        (float4*)d_out);

    // join: capture stream waits for the side branch
    cudaEventRecord(eJoin, s1);
    cudaStreamWaitEvent(0, eJoin, 0);
}